// round 13
// baseline (speedup 1.0000x reference)
#include <cuda_runtime.h>
#include <cuda_bf16.h>
#include <cstdint>
#include <math_constants.h>

#define B_ 64
#define L_ 1024
#define P_ 2047
#define NS 16
#define SBI 272                 // interleaved tile row stride (bytes)
#define TI  (64 * SBI)          // 17408 B per 64-row tile
#define RGS 132                 // ring row stride (floats): 2 slots x 64 + pad

#define O_Q  0
#define O_R  (O_Q + TI)
#define O_K  (O_R + TI)
#define O_P  (O_K + TI)
#define O_G  (O_P + TI)
#define O_ST (O_G + 64 * RGS * 4)
#define O_MC (O_ST + 64 * 4 * 8)
#define SMEMB (O_MC + 16)

__device__ __forceinline__ uint32_t smem_u32(const void* p) {
    uint32_t a;
    asm("{ .reg .u64 t; cvta.to.shared.u64 t, %1; cvt.u32.u64 %0, t; }" : "=r"(a) : "l"(p));
    return a;
}
#define LDSM4(r, a) \
    asm volatile("ldmatrix.sync.aligned.m8n8.x4.shared.b16 {%0,%1,%2,%3}, [%4];" \
        : "=r"((r)[0]), "=r"((r)[1]), "=r"((r)[2]), "=r"((r)[3]) : "r"(a))
#define LDSM4T(r, a) \
    asm volatile("ldmatrix.sync.aligned.m8n8.x4.trans.shared.b16 {%0,%1,%2,%3}, [%4];" \
        : "=r"((r)[0]), "=r"((r)[1]), "=r"((r)[2]), "=r"((r)[3]) : "r"(a))
#define MMA(c, a, b) \
    asm volatile("mma.sync.aligned.m16n8k16.row.col.f32.bf16.bf16.f32 " \
        "{%0,%1,%2,%3}, {%4,%5,%6,%7}, {%8,%9}, {%0,%1,%2,%3};" \
        : "+f"((c)[0]), "+f"((c)[1]), "+f"((c)[2]), "+f"((c)[3]) \
        : "r"((a)[0]), "r"((a)[1]), "r"((a)[2]), "r"((a)[3]), "r"((b)[0]), "r"((b)[1]))

__device__ __forceinline__ uint32_t pk2(float a, float b) {
    return (uint32_t)__bfloat16_as_ushort(__float2bfloat16(a)) |
           ((uint32_t)__bfloat16_as_ushort(__float2bfloat16(b)) << 16);
}
__device__ __forceinline__ float bfres(float x) {
    return x - __bfloat162float(__float2bfloat16(x));
}
__device__ __forceinline__ void st_blk(char* sm, int oT, int r, int bl, float4 a, float4 b) {
    uint4 hi = make_uint4(pk2(a.x, a.y), pk2(a.z, a.w), pk2(b.x, b.y), pk2(b.z, b.w));
    uint4 lo = make_uint4(pk2(bfres(a.x), bfres(a.y)), pk2(bfres(a.z), bfres(a.w)),
                          pk2(bfres(b.x), bfres(b.y)), pk2(bfres(b.z), bfres(b.w)));
    char* p = sm + oT + r * SBI + bl * 32;
    *(uint4*)p = hi;
    *(uint4*)(p + 16) = lo;
}
__device__ __forceinline__ void merge_ms(float& m, float& s, float om, float os) {
    float nm = fmaxf(m, om);
    float base = (nm == -CUDART_INF_F) ? 0.f : nm;
    s = s * __expf(m - base) + os * __expf(om - base);
    m = nm;
}

__global__ __launch_bounds__(256, 2)
void fused_mma_kernel(const float* __restrict__ q, const float* __restrict__ kk,
                      const float* __restrict__ v, const float* __restrict__ pos,
                      const char* __restrict__ maskp, float* __restrict__ out,
                      float* __restrict__ attn) {
    extern __shared__ char sm[];
    const uint32_t sb = smem_u32(sm);
    const int tid = threadIdx.x;
    const int lane = tid & 31, w = tid >> 5;
    const int wr = w & 3, wc = w >> 2;
    const int b = blockIdx.y, l0 = blockIdx.x * 64;

    const float* qb = q + (size_t)b * L_ * 64;
    const float* kb = kk + (size_t)b * L_ * 64;
    const float* vb = v + (size_t)b * L_ * 64;
    const float* pb = pos + (size_t)b * P_ * 64;

    float* ring = (float*)(sm + O_G);
    float2* stp = (float2*)(sm + O_ST);
    int* cnt = (int*)(sm + O_MC);

    // ---- mask dtype detection (first 8KB) ----
    if (tid < 2) cnt[tid] = 0;
    __syncthreads();
    {
        int c0 = 0, c1 = 0;
        #pragma unroll
        for (int e = 0; e < 2; e++) {
            uint4 u = ((const uint4*)maskp)[tid * 2 + e];
            uint32_t ws[4] = {u.x, u.y, u.z, u.w};
            #pragma unroll
            for (int wd = 0; wd < 4; wd++) {
                c0 += ((ws[wd] & 0x000000ffu) != 0);
                c1 += ((ws[wd] & 0x0000ff00u) != 0);
            }
        }
        if (c0) atomicAdd(&cnt[0], c0);
        if (c1) atomicAdd(&cnt[1], c1);
    }

    // ---- tile fills ----
    auto fill_QR = [&]() {
        #pragma unroll
        for (int e = 0; e < 2; e++) {
            int tt = tid + e * 256, r = tt & 63, bl = tt >> 6;
            const float* ap = qb + (size_t)(l0 + r) * 64 + bl * 8;
            float4 a0 = *(const float4*)ap, a1 = *(const float4*)(ap + 4);
            a0.x *= .125f; a0.y *= .125f; a0.z *= .125f; a0.w *= .125f;
            a1.x *= .125f; a1.y *= .125f; a1.z *= .125f; a1.w *= .125f;
            st_blk(sm, O_Q, r, bl, a0, a1);
            const float* rp = qb + (size_t)(L_ - 1 - (l0 + r)) * 64 + bl * 8;
            float4 r0v = *(const float4*)rp, r1v = *(const float4*)(rp + 4);
            r0v.x *= .125f; r0v.y *= .125f; r0v.z *= .125f; r0v.w *= .125f;
            r1v.x *= .125f; r1v.y *= .125f; r1v.z *= .125f; r1v.w *= .125f;
            st_blk(sm, O_R, r, bl, r0v, r1v);
        }
    };
    auto fill_K = [&](int t) {
        #pragma unroll
        for (int e = 0; e < 2; e++) {
            int tt = tid + e * 256, r = tt & 63, bl = tt >> 6;
            const float* ap = kb + (size_t)(t * 64 + r) * 64 + bl * 8;
            st_blk(sm, O_K, r, bl, *(const float4*)ap, *(const float4*)(ap + 4));
        }
    };
    auto fill_V = [&](int t) {
        #pragma unroll
        for (int e = 0; e < 2; e++) {
            int tt = tid + e * 256, r = tt & 63, bl = tt >> 6;
            const float* ap = vb + (size_t)(t * 64 + r) * 64 + bl * 8;
            st_blk(sm, O_K, r, bl, *(const float4*)ap, *(const float4*)(ap + 4));
        }
    };
    auto fill_P = [&](int win) {
        #pragma unroll
        for (int e = 0; e < 2; e++) {
            int tt = tid + e * 256, r = tt & 63, bl = tt >> 6;
            int pr = l0 + 64 * win + r; if (pr > P_ - 1) pr = P_ - 1;
            const float* ap = pb + (size_t)pr * 64 + bl * 8;
            st_blk(sm, O_P, r, bl, *(const float4*)ap, *(const float4*)(ap + 4));
        }
    };

    fill_QR(); fill_K(0); fill_P(0);
    __syncthreads();
    const int mode = (cnt[0] > 0 && cnt[1] > 0) ? 0 : 1;

    auto adA = [&](int oT, int kc, int hi) -> uint32_t {
        int row = 16 * wr + (lane & 15), blk = 2 * kc + (lane >> 4);
        return sb + oT + row * SBI + blk * 32 + (hi ? 0 : 16);
    };
    auto adB = [&](int oT, int np, int kc, int hi) -> uint32_t {
        int nrow = 32 * wc + 16 * np + 8 * (lane >> 4) + (lane & 7);
        int blk = 2 * kc + ((lane >> 3) & 1);
        return sb + oT + nrow * SBI + blk * 32 + (hi ? 0 : 16);
    };
    auto adBT = [&](int oT, int np, int kc2, int hi) -> uint32_t {
        int krow = 32 * wc + 16 * kc2 + (lane & 15);
        int blk = 2 * np + (lane >> 4);
        return sb + oT + krow * SBI + blk * 32 + (hi ? 0 : 16);
    };

    const int r0 = 16 * wr + (lane >> 2), c2 = lane & 3;
    const int rr = tid >> 2, qq = tid & 3;

    uint32_t Qh[4][4], Ql[4][4], Rh[4][4];
    #pragma unroll
    for (int kc = 0; kc < 4; kc++) {
        LDSM4(Qh[kc], adA(O_Q, kc, 1));
        LDSM4(Ql[kc], adA(O_Q, kc, 0));
        LDSM4(Rh[kc], adA(O_R, kc, 1));
    }

    auto gemm_S = [&](float acc[4][4]) {
        #pragma unroll
        for (int kc = 0; kc < 4; kc++)
            #pragma unroll
            for (int np = 0; np < 2; np++) {
                uint32_t bh[4], bl_[4];
                LDSM4(bh, adB(O_K, np, kc, 1));
                MMA(acc[2 * np], Qh[kc], bh);     MMA(acc[2 * np], Ql[kc], bh);
                MMA(acc[2 * np + 1], Qh[kc], bh + 2); MMA(acc[2 * np + 1], Ql[kc], bh + 2);
                LDSM4(bl_, adB(O_K, np, kc, 0));
                MMA(acc[2 * np], Qh[kc], bl_);    MMA(acc[2 * np + 1], Qh[kc], bl_ + 2);
            }
    };
    auto gemm_G = [&](float acc[4][4]) {
        #pragma unroll
        for (int kc = 0; kc < 4; kc++) {
            uint32_t rl[4];
            LDSM4(rl, adA(O_R, kc, 0));
            #pragma unroll
            for (int np = 0; np < 2; np++) {
                uint32_t bh[4], bl_[4];
                LDSM4(bh, adB(O_P, np, kc, 1));
                MMA(acc[2 * np], Rh[kc], bh);     MMA(acc[2 * np], rl, bh);
                MMA(acc[2 * np + 1], Rh[kc], bh + 2); MMA(acc[2 * np + 1], rl, bh + 2);
                LDSM4(bl_, adB(O_P, np, kc, 0));
                MMA(acc[2 * np], Rh[kc], bl_);    MMA(acc[2 * np + 1], Rh[kc], bl_ + 2);
            }
        }
    };
    // shifted ring store: G[i][c] -> ring[i][slot*64 + ((c - i) & 63)]
    // sc parity == i parity (c even): even rows use STS.64, odd rows scalar STS.32
    auto ring_store = [&](float acc[4][4], int slot) {
        #pragma unroll
        for (int nf = 0; nf < 4; nf++) {
            int c = 32 * wc + 8 * nf + 2 * c2;
            #pragma unroll
            for (int h = 0; h < 2; h++) {
                int i = r0 + 8 * h;
                int sc = (c - i) & 63;
                float* bp = ring + i * RGS + slot * 64;
                if ((i & 1) == 0) {
                    *(float2*)(bp + sc) = make_float2(acc[nf][2 * h], acc[nf][2 * h + 1]);
                } else {
                    bp[sc] = acc[nf][2 * h];
                    bp[(sc + 1) & 63] = acc[nf][2 * h + 1];
                }
            }
        }
    };

    // ---- prologue G0 ----
    {
        float accG[4][4] = {};
        gemm_G(accG);
        __syncthreads();
        ring_store(accG, 0);
        fill_P(1);
        __syncthreads();
    }

    float run_m = -CUDART_INF_F, run_s = 0.f;

    // ================= phase 1 =================
    for (int t = 0; t < NS; t++) {
        float accS[4][4] = {};
        float accG[4][4] = {};
        gemm_S(accS);
        gemm_G(accG);
        __syncthreads();
        ring_store(accG, (t + 1) & 1);
        if (t < NS - 1) fill_K(t + 1);
        fill_P(t + 2);
        __syncthreads();
        const int sbit = t & 1;
        // fragment domain: bias add (shifted ring: bias(i,j) = slot[i][j]) + x write in place
        #pragma unroll
        for (int nf = 0; nf < 4; nf++) {
            int j0 = 32 * wc + 8 * nf + 2 * c2;
            #pragma unroll
            for (int h = 0; h < 2; h++) {
                int i = r0 + 8 * h;
                float* bp = ring + i * RGS;
                // bias for cols j0, j0+1: slot = sbit while i+j < 64 else other slot
                int sl0 = (i + j0 < 64) ? sbit : (sbit ^ 1);
                int sl1 = (i + j0 + 1 < 64) ? sbit : (sbit ^ 1);
                float b0, b1;
                if (sl0 == sl1) {
                    float2 bb = *(const float2*)(bp + sl0 * 64 + j0);
                    b0 = bb.x; b1 = bb.y;
                } else {
                    b0 = bp[sl0 * 64 + j0];
                    b1 = bp[sl1 * 64 + j0 + 1];
                }
                *(float2*)(bp + sbit * 64 + j0) =
                    make_float2(accS[nf][2 * h] + b0, accS[nf][2 * h + 1] + b1);
            }
        }
        __syncthreads();
        // row domain: mask + stats + coalesced logit store
        {
            float xs[16];
            const float* xr = ring + rr * RGS + sbit * 64 + qq * 16;
            #pragma unroll
            for (int e = 0; e < 4; e++) {
                float4 vv = *(const float4*)(xr + 4 * e);
                xs[4 * e] = vv.x; xs[4 * e + 1] = vv.y; xs[4 * e + 2] = vv.z; xs[4 * e + 3] = vv.w;
            }
            size_t gb = ((size_t)b * L_ + l0 + rr) * L_ + t * 64 + qq * 16;
            if (mode == 0) {
                uint4 mv = *(const uint4*)(maskp + gb);
                uint32_t ws[4] = {mv.x, mv.y, mv.z, mv.w};
                #pragma unroll
                for (int wd = 0; wd < 4; wd++) {
                    if (ws[wd] & 0x000000ffu) xs[4 * wd] = -CUDART_INF_F;
                    if (ws[wd] & 0x0000ff00u) xs[4 * wd + 1] = -CUDART_INF_F;
                    if (ws[wd] & 0x00ff0000u) xs[4 * wd + 2] = -CUDART_INF_F;
                    if (ws[wd] & 0xff000000u) xs[4 * wd + 3] = -CUDART_INF_F;
                }
            } else {
                const uint4* mp = (const uint4*)((const uint32_t*)maskp + gb);
                #pragma unroll
                for (int e = 0; e < 4; e++) {
                    uint4 mv = mp[e];
                    if (mv.x) xs[4 * e] = -CUDART_INF_F;
                    if (mv.y) xs[4 * e + 1] = -CUDART_INF_F;
                    if (mv.z) xs[4 * e + 2] = -CUDART_INF_F;
                    if (mv.w) xs[4 * e + 3] = -CUDART_INF_F;
                }
            }
            #pragma unroll
            for (int e = 0; e < 4; e++)
                *(float4*)(attn + gb + 4 * e) =
                    make_float4(xs[4 * e], xs[4 * e + 1], xs[4 * e + 2], xs[4 * e + 3]);
            float lm = xs[0];
            #pragma unroll
            for (int j = 1; j < 16; j++) lm = fmaxf(lm, xs[j]);
            float nm = fmaxf(run_m, lm);
            float base = (nm == -CUDART_INF_F) ? 0.f : nm;
            float es = 0.f;
            #pragma unroll
            for (int j = 0; j < 16; j++) es += __expf(xs[j] - base);
            run_s = run_s * __expf(run_m - base) + es;
            run_m = nm;
        }
    }

    // ---- merge per-quarter stats -> per-row M, inv ----
    stp[rr * 4 + qq] = make_float2(run_m, run_s);
    __syncthreads();
    float Mu, inv;
    {
        float2 a0 = stp[rr * 4 + 0];
        float m = a0.x, s = a0.y;
        #pragma unroll
        for (int e = 1; e < 4; e++) { float2 ae = stp[rr * 4 + e]; merge_ms(m, s, ae.x, ae.y); }
        Mu = (m == -CUDART_INF_F) ? 0.f : m;
        inv = 1.f / s;
    }
    __syncthreads();

    // ================= phase 2: probs + O = P@V =================
    float accO[8][4] = {};
    for (int t = 0; t < NS; t++) {
        {
            size_t gb = ((size_t)b * L_ + l0 + rr) * L_ + t * 64 + qq * 16;
            float4 pv[4];
            #pragma unroll
            for (int e = 0; e < 4; e++) {
                float4 xv = *(const float4*)(attn + gb + 4 * e);
                pv[e] = make_float4(__expf(xv.x - Mu) * inv, __expf(xv.y - Mu) * inv,
                                    __expf(xv.z - Mu) * inv, __expf(xv.w - Mu) * inv);
                *(float4*)(attn + gb + 4 * e) = pv[e];
            }
            st_blk(sm, O_P, rr, 2 * qq, pv[0], pv[1]);
            st_blk(sm, O_P, rr, 2 * qq + 1, pv[2], pv[3]);
        }
        fill_V(t);
        __syncthreads();
        #pragma unroll
        for (int kk = 0; kk < 2; kk++) {
            int kc = 2 * wc + kk;
            uint32_t Ph[4], Pl[4];
            LDSM4(Ph, adA(O_P, kc, 1));
            LDSM4(Pl, adA(O_P, kc, 0));
            #pragma unroll
            for (int np = 0; np < 4; np++) {
                uint32_t bh[4], bl_[4];
                LDSM4T(bh, adBT(O_K, np, kk, 1));
                MMA(accO[2 * np], Ph, bh);     MMA(accO[2 * np], Pl, bh);
                MMA(accO[2 * np + 1], Ph, bh + 2); MMA(accO[2 * np + 1], Pl, bh + 2);
                LDSM4T(bl_, adBT(O_K, np, kk, 0));
                MMA(accO[2 * np], Ph, bl_);    MMA(accO[2 * np + 1], Ph, bl_ + 2);
            }
        }
        __syncthreads();
    }
    // ---- split-k reduction ----
    if (wc == 0) {
        #pragma unroll
        for (int g = 0; g < 8; g++) {
            int j0 = 8 * g + 2 * c2;
            #pragma unroll
            for (int h = 0; h < 2; h++)
                *(float2*)(ring + (r0 + 8 * h) * RGS + j0) =
                    make_float2(accO[g][2 * h], accO[g][2 * h + 1]);
        }
    }
    __syncthreads();
    if (wc == 1) {
        #pragma unroll
        for (int g = 0; g < 8; g++) {
            int j0 = 8 * g + 2 * c2;
            #pragma unroll
            for (int h = 0; h < 2; h++) {
                int i = r0 + 8 * h;
                float2 pp = *(const float2*)(ring + i * RGS + j0);
                *(float2*)(out + ((size_t)b * L_ + l0 + i) * 64 + j0) =
                    make_float2(accO[g][2 * h] + pp.x, accO[g][2 * h + 1] + pp.y);
            }
        }
    }
}

extern "C" void kernel_launch(void* const* d_in, const int* in_sizes, int n_in,
                              void* d_out, int out_size) {
    const float* q = (const float*)d_in[0];
    const float* k = (const float*)d_in[1];
    const float* v = (const float*)d_in[2];
    const float* pos = (const float*)d_in[3];
    const char* msk = (const char*)d_in[4];
    float* out = (float*)d_out;
    float* attn = out + (size_t)B_ * L_ * 64;

    cudaFuncSetAttribute(fused_mma_kernel,
                         cudaFuncAttributeMaxDynamicSharedMemorySize, SMEMB);
    fused_mma_kernel<<<dim3(16, B_), 256, SMEMB>>>(q, k, v, pos, msk, out, attn);
}